// round 13
// baseline (speedup 1.0000x reference)
#include <cuda_runtime.h>
#include <cuda_fp16.h>
#include <math.h>

#define V    256
#define HA   2048
#define HHP  4096
#define HS   2048
#define DEPTH 12
#define NB   148
#define NT   1024

// ---------------- fp16 weight storage ----------------
__device__ __align__(16) __half g_W_ih_a[4 * HA * V];
__device__ __align__(16) __half g_W_hh_a[4 * HA * HA];
__device__ __align__(16) __half g_W_out_a[V * HA];
__device__ __align__(16) __half g_W_out_aT[HA * V];     // transposed copy
__device__ __align__(16) __half g_W_sum[HS * HHP];
__device__ __align__(16) __half g_W_ih_hp[4 * HHP * (2 * V)];
__device__ __align__(16) __half g_W_hh_hp[4 * HHP * HHP];   // filled lazily in P1(0)
__device__ __align__(16) __half g_W_out_hp[V * HHP];

// ---------------- persistent state ----------------
__device__ __align__(16) float g_h_a[2][HA];
__device__ __align__(16) float g_c_a[2][HA];
__device__ __align__(16) float g_c_hp[2][HHP];
__device__ __align__(16) float g_h_hp[HHP];
__device__ __align__(16) float g_h_sum[HS];
__device__ __align__(16) float g_pA[NB * V];            // per-block logits_a partials
__device__ __align__(16) float g_logits_hp[V];

__device__ unsigned g_bar_count = 0;
__device__ unsigned g_bar_gen = 0;

__device__ __forceinline__ float sigm(float x) { return 1.f / (1.f + expf(-x)); }

__device__ __forceinline__ float wred(float v) {
    #pragma unroll
    for (int o = 16; o; o >>= 1) v += __shfl_xor_sync(0xffffffffu, v, o);
    return v;
}

// lane-strided partial dot: fp16 weights vs fp16 x (smem); half2 FMA per 8-seg, fp32 across
template <bool STREAM>
__device__ __forceinline__ float dot8h(const __half* __restrict__ W,
                                       const __half* __restrict__ xh,
                                       int n8, int lane) {
    const int4* __restrict__ W4 = (const int4*)W;
    const int4* __restrict__ X4 = (const int4*)xh;
    float s = 0.f;
    #pragma unroll 4
    for (int t = lane; t < n8; t += 32) {
        int4 w = STREAM ? __ldcs(W4 + t) : __ldg(W4 + t);
        int4 x = X4[t];
        __half2 acc = __hmul2(*(__half2*)&w.x, *(__half2*)&x.x);
        acc = __hfma2(*(__half2*)&w.y, *(__half2*)&x.y, acc);
        acc = __hfma2(*(__half2*)&w.z, *(__half2*)&x.z, acc);
        acc = __hfma2(*(__half2*)&w.w, *(__half2*)&x.w, acc);
        float2 f = __half22float2(acc);
        s += f.x + f.y;
    }
    return s;
}

// ---------------- fp32 -> fp16 conversion (all but W_hh_hp) ----------------
__global__ void convert_kernel(const float* __restrict__ s0, const float* __restrict__ s1,
                               const float* __restrict__ s2, const float* __restrict__ s3,
                               const float* __restrict__ s4, const float* __restrict__ s5) {
    const size_t n0 = 4ull * HA * V, n1 = 4ull * HA * HA, n2 = (size_t)V * HA,
                 n3 = (size_t)HS * HHP, n4 = 4ull * HHP * 2 * V, n5 = (size_t)V * HHP;
    const size_t tot4 = (n0 + n1 + n2 + n3 + n4 + n5) / 4;
    for (size_t i4 = blockIdx.x * (size_t)blockDim.x + threadIdx.x; i4 < tot4;
         i4 += (size_t)gridDim.x * blockDim.x) {
        size_t i = i4 * 4;
        const float* s; __half* d;
        if (i < n0)              { s = s0; d = g_W_ih_a; }
        else if ((i -= n0) < n1) { s = s1; d = g_W_hh_a; }
        else if ((i -= n1) < n2) { s = s2; d = g_W_out_a; }
        else if ((i -= n2) < n3) { s = s3; d = g_W_sum; }
        else if ((i -= n3) < n4) { s = s4; d = g_W_ih_hp; }
        else                     { i -= n4; s = s5; d = g_W_out_hp; }
        float4 v = __ldcs((const float4*)(s + i));
        __half2 lo = __floats2half2_rn(v.x, v.y);
        __half2 hi = __floats2half2_rn(v.z, v.w);
        uint2 u = make_uint2(*(unsigned*)&lo, *(unsigned*)&hi);
        __stcs((uint2*)(d + i), u);
    }
}

// transpose W_out_a (fp32 [V][HA]) -> g_W_out_aT (fp16 [HA][V])
__global__ void transpose_kernel(const float* __restrict__ W) {
    int i = blockIdx.x * blockDim.x + threadIdx.x;   // i < HA*V/8
    if (i >= HA * V / 8) return;
    int c  = i >> 5;            // column of W (0..HA-1)
    int r0 = (i & 31) * 8;      // 8 consecutive rows
    __half h[8];
    #pragma unroll
    for (int k = 0; k < 8; ++k) h[k] = __float2half(W[(size_t)(r0 + k) * HA + c]);
    *(int4*)(g_W_out_aT + (size_t)c * V + r0) = *(int4*)h;
}

// ---------------- grid barrier ----------------
#define GSYNC() do {                                                         \
    __syncthreads();                                                         \
    ++nb;                                                                    \
    if (tid == 0) {                                                          \
        __threadfence();                                                     \
        if (atomicAdd(&g_bar_count, 1u) == NB - 1) {                         \
            atomicExch(&g_bar_count, 0u);                                    \
            __threadfence();                                                 \
            atomicAdd(&g_bar_gen, 1u);                                       \
        } else {                                                             \
            while ((int)(*(volatile unsigned*)&g_bar_gen - (gen0 + nb)) < 0) \
                __nanosleep(64);                                             \
        }                                                                    \
        __threadfence();                                                     \
    }                                                                        \
    __syncthreads();                                                         \
} while (0)

__device__ __forceinline__ void stage_half(const float* __restrict__ g,
                                           __half* __restrict__ sh, int n, int tid) {
    for (int t = tid; t < n / 8; t += NT) {
        float4 v1 = __ldcg((const float4*)g + 2 * t);
        float4 v2 = __ldcg((const float4*)g + 2 * t + 1);
        __half2 h0 = __floats2half2_rn(v1.x, v1.y);
        __half2 h1 = __floats2half2_rn(v1.z, v1.w);
        __half2 h2 = __floats2half2_rn(v2.x, v2.y);
        __half2 h3 = __floats2half2_rn(v2.z, v2.w);
        int4 o;
        o.x = *(int*)&h0; o.y = *(int*)&h1; o.z = *(int*)&h2; o.w = *(int*)&h3;
        ((int4*)sh)[t] = o;
    }
}

// value-based block softmax over V; all threads participate (tid<V active)
__device__ __forceinline__ void softmax_v(float lv, float* __restrict__ outF,
                                          __half* __restrict__ outH,
                                          float* sred, float* sbc,
                                          int tid, int lane, int warp) {
    if (tid < V) {
        float m = lv;
        #pragma unroll
        for (int o = 16; o; o >>= 1) m = fmaxf(m, __shfl_xor_sync(0xffffffffu, m, o));
        if (lane == 0) sred[warp] = m;
    }
    __syncthreads();
    if (tid == 0) {
        float m = sred[0];
        #pragma unroll
        for (int k = 1; k < 8; ++k) m = fmaxf(m, sred[k]);
        sbc[0] = m;
    }
    __syncthreads();
    float ev = 0.f;
    if (tid < V) {
        ev = expf(lv - sbc[0]);
        float ss = wred(ev);
        if (lane == 0) sred[warp] = ss;
    }
    __syncthreads();
    if (tid < V) {
        float bs = sred[0] + sred[1] + sred[2] + sred[3]
                 + sred[4] + sred[5] + sred[6] + sred[7];
        float r = ev / bs;
        outH[tid] = __float2half(r);
        if (outF) outF[tid] = r;
    }
    __syncthreads();
}

// distributed logit rows (epilogue): fp16 W rows dot fp32 x (global)
__device__ __forceinline__ void logits_rows(const __half* __restrict__ W,
                                            const float* __restrict__ bias,
                                            const float* __restrict__ x, int C,
                                            float* __restrict__ gl, int r0, int r1,
                                            float* sred, int tid, int lane, int warp) {
    for (int row = r0; row < r1; ++row) {
        float p = 0.f;
        if (tid < C / 8) {
            int4 w = __ldg((const int4*)(W + (size_t)row * C) + tid);
            float4 xa4 = __ldcg((const float4*)x + 2 * tid);
            float4 xb4 = __ldcg((const float4*)x + 2 * tid + 1);
            float2 w0 = __half22float2(*(__half2*)&w.x);
            float2 w1 = __half22float2(*(__half2*)&w.y);
            float2 w2 = __half22float2(*(__half2*)&w.z);
            float2 w3 = __half22float2(*(__half2*)&w.w);
            p = fmaf(w0.x, xa4.x, fmaf(w0.y, xa4.y, fmaf(w1.x, xa4.z, fmaf(w1.y, xa4.w,
                fmaf(w2.x, xb4.x, fmaf(w2.y, xb4.y, fmaf(w3.x, xb4.z, w3.y * xb4.w)))))));
        }
        p = wred(p);
        if (lane == 0) sred[warp] = p;
        __syncthreads();
        if (warp == 0) {
            float v = sred[lane];
            v = wred(v);
            if (lane == 0) gl[row] = v + __ldg(bias + row);
        }
        __syncthreads();
    }
}

__global__ __launch_bounds__(NT, 1) void persist_kernel(
    const float* __restrict__ xa, const float* __restrict__ xhp,
    const float* __restrict__ Whhhp32,
    const float* __restrict__ biha, const float* __restrict__ bhha,
    const float* __restrict__ bouta, const float* __restrict__ bsum,
    const float* __restrict__ bihhp, const float* __restrict__ bhhhp,
    const float* __restrict__ bouthp, float* __restrict__ out) {
    __shared__ __align__(16) __half s_aa[2 * V];     // [a | a_hp]
    __shared__ __align__(16) __half s_hA[HA];
    __shared__ __align__(16) __half s_hhp[HHP];
    __shared__ __align__(16) __half s_chp[HHP];
    __shared__ float s_hAloc[16];
    __shared__ float pA[112], pS[56], pH[448], pL[8], pIH[112];
    __shared__ float sred[32], sbc[2];
    __shared__ unsigned s_gen0;

    const int tid = threadIdx.x, lane = tid & 31, warp = tid >> 5;
    const int b = blockIdx.x;

    if (tid == 0) s_gen0 = atomicAdd(&g_bar_gen, 0u);
    __syncthreads();
    const unsigned gen0 = s_gen0;
    unsigned nb = 0;

    // ---- init ----
    {
        int gt = b * NT + tid;
        if (gt < HA)  { g_h_a[0][gt] = xa[gt];  g_c_a[0][gt] = 0.f; }
        if (gt < HHP) { g_h_hp[gt]   = xhp[gt]; g_c_hp[0][gt] = 0.f; }
        if (tid < 2 * V) s_aa[tid] = __float2half(1.f / V);
    }
    GSYNC();

    const int uA0 = (b * HA) / NB,  uA1 = ((b + 1) * HA) / NB;
    const int rS0 = (b * HS) / NB,  rS1 = ((b + 1) * HS) / NB;
    const int uH0 = (b * HHP) / NB, uH1 = ((b + 1) * HHP) / NB;
    const int rO0 = (b * V) / NB,   rO1 = ((b + 1) * V) / NB;
    const int nuA = uA1 - uA0, nrA = 4 * nuA;
    const int nrS = rS1 - rS0;
    const int nuH = uH1 - uH0, nrH = 4 * nuH;
    const int nrO = rO1 - rO0;
    const int nA2 = nrA * 2, nS4 = nrS * 4, nH4 = nrH * 4, nL4 = nrO * 4;
    const int ntot = nA2 + nS4 + nH4 + nL4;

    for (int s = 0; s < DEPTH; ++s) {
        const int pp = s & 1;
        const float* hA_in  = g_h_a[pp];   float* hA_out  = g_h_a[pp ^ 1];
        const float* cA_in  = g_c_a[pp];   float* cA_out  = g_c_a[pp ^ 1];
        const float* cHP_in = g_c_hp[pp];  float* cHP_out = g_c_hp[pp ^ 1];

        // ======== P1: all streaming matvecs ========
        stage_half(hA_in,  s_hA,  HA,  tid);
        stage_half(g_h_hp, s_hhp, HHP, tid);
        stage_half(cHP_in, s_chp, HHP, tid);
        if (s == 0) {
            // lazily convert this block's W_hh_hp rows to fp16 (hh·c_hp == 0 this step)
            for (int t = tid; t < nrH * 512; t += NT) {
                int r = t >> 9, o = t & 511;
                int u = r >> 2, g = r & 3;
                size_t row = (size_t)(g * HHP + uH0 + u);
                const float4* src = (const float4*)(Whhhp32 + row * HHP) + 2 * o;
                float4 v1 = __ldcs(src), v2 = __ldcs(src + 1);
                __half2 h0 = __floats2half2_rn(v1.x, v1.y);
                __half2 h1 = __floats2half2_rn(v1.z, v1.w);
                __half2 h2 = __floats2half2_rn(v2.x, v2.y);
                __half2 h3 = __floats2half2_rn(v2.z, v2.w);
                int4 w;
                w.x = *(int*)&h0; w.y = *(int*)&h1; w.z = *(int*)&h2; w.w = *(int*)&h3;
                __stcs((int4*)(g_W_hh_hp + row * HHP) + o, w);
            }
        }
        __syncthreads();

        for (int t = warp; t < ntot; t += 32) {
            float p;
            if (t < nA2) {
                int r = t >> 1, c = t & 1;
                int u = r >> 2, g = r & 3;
                size_t row = (size_t)(g * HA + uA0 + u);
                if (c == 0)
                    p = dot8h<false>(g_W_ih_a + row * V, s_aa, V / 8, lane)
                      + dot8h<false>(g_W_hh_a + row * HA, s_hA, 128, lane);
                else
                    p = dot8h<false>(g_W_hh_a + row * HA + 1024, s_hA + 1024, 128, lane);
                p = wred(p);
                if (lane == 0) pA[t] = p;
            } else if (t < nA2 + nS4) {
                int t2 = t - nA2, r = t2 >> 2, c = t2 & 3;
                size_t row = (size_t)(rS0 + r);
                p = dot8h<false>(g_W_sum + row * HHP + c * 1024, s_hhp + c * 1024, 128, lane);
                p = wred(p);
                if (lane == 0) pS[t2] = p;
            } else if (t < nA2 + nS4 + nH4) {
                int t3 = t - nA2 - nS4;
                if (s == 0) {
                    if (lane == 0) pH[t3] = 0.f;
                } else {
                    int r = t3 >> 2, c = t3 & 3;
                    int u = r >> 2, g = r & 3;
                    size_t row = (size_t)(g * HHP + uH0 + u);
                    p = dot8h<true>(g_W_hh_hp + row * HHP + c * 1024, s_chp + c * 1024, 128, lane);
                    p = wred(p);
                    if (lane == 0) pH[t3] = p;
                }
            } else {
                int t4 = t - nA2 - nS4 - nH4, r = t4 >> 2, c = t4 & 3;
                size_t row = (size_t)(rO0 + r);
                p = dot8h<false>(g_W_out_hp + row * HHP + c * 1024, s_hhp + c * 1024, 128, lane);
                p = wred(p);
                if (lane == 0) pL[t4] = p;
            }
        }
        __syncthreads();
        // arch elementwise (this block's hA slice) + h_sum + logits_hp(s-1)
        for (int u = tid; u < nuA; u += NT) {
            int j = uA0 + u;
            float gv[4];
            #pragma unroll
            for (int g = 0; g < 4; ++g)
                gv[g] = pA[(u * 4 + g) * 2] + pA[(u * 4 + g) * 2 + 1]
                      + __ldg(biha + g * HA + j) + __ldg(bhha + g * HA + j);
            float gi = sigm(gv[0]), gf = sigm(gv[1]), gg = tanhf(gv[2]), go = sigm(gv[3]);
            float cn = gf * __ldcg(cA_in + j) + gi * gg;
            cA_out[j] = cn;
            float hv = go * tanhf(cn);
            hA_out[j] = hv;
            s_hAloc[u] = hv;
        }
        for (int r = tid; r < nrS; r += NT) {
            int row = rS0 + r;
            float v = pS[r * 4] + pS[r * 4 + 1] + pS[r * 4 + 2] + pS[r * 4 + 3]
                    + __ldg(bsum + row);
            g_h_sum[row] = fmaxf(v, 0.f);
        }
        for (int r = tid; r < nrO; r += NT) {
            int row = rO0 + r;
            g_logits_hp[row] = pL[r * 4] + pL[r * 4 + 1] + pL[r * 4 + 2] + pL[r * 4 + 3]
                             + __ldg(bouthp + row);
        }
        __syncthreads();
        // partial logits_a over this block's hA slice (transposed weights)
        if (tid < V) {
            float acc = 0.f;
            for (int c = 0; c < nuA; ++c)
                acc = fmaf(__half2float(__ldg(g_W_out_aT + (size_t)(uA0 + c) * V + tid)),
                           s_hAloc[c], acc);
            g_pA[b * V + tid] = acc;
        }
        GSYNC();

        // ======== P2: softmaxes + ih dots + hp elementwise ========
        if (s > 0) {
            float lv = (tid < V) ? __ldcg(g_logits_hp + tid) : 0.f;
            softmax_v(lv, (b == 0) ? (out + DEPTH * V + (s - 1) * V) : nullptr,
                      s_aa + V, sred, sbc, tid, lane, warp);
        }
        {
            float lv = 0.f;
            if (tid < V) {
                const float* p = g_pA + tid;
                #pragma unroll 4
                for (int k = 0; k < NB; ++k) lv += __ldcg(p + k * V);
                lv += __ldg(bouta + tid);
            }
            softmax_v(lv, (b == 0) ? (out + s * V) : nullptr,
                      s_aa, sred, sbc, tid, lane, warp);
        }
        for (int r = warp; r < nrH; r += 32) {
            int u = r >> 2, g = r & 3;
            size_t row = (size_t)(g * HHP + uH0 + u);
            float p = dot8h<false>(g_W_ih_hp + row * (2 * V), s_aa, (2 * V) / 8, lane);
            p = wred(p);
            if (lane == 0) pIH[r] = p;
        }
        __syncthreads();
        for (int u = tid; u < nuH; u += NT) {
            int j = uH0 + u;
            float gv[4];
            #pragma unroll
            for (int g = 0; g < 4; ++g) {
                int r = u * 4 + g;
                gv[g] = pH[r * 4] + pH[r * 4 + 1] + pH[r * 4 + 2] + pH[r * 4 + 3]
                      + pIH[r]
                      + __ldg(bihhp + g * HHP + j) + __ldg(bhhhp + g * HHP + j);
            }
            float gi = sigm(gv[0]), gf = sigm(gv[1]), gg = tanhf(gv[2]), go = sigm(gv[3]);
            float cold = (j < HA) ? __ldcg(hA_out + j) : __ldcg(g_h_sum + (j - HA));
            float cn = gf * cold + gi * gg;
            cHP_out[j] = cn;
            g_h_hp[j] = go * tanhf(cn);
        }
        GSYNC();
    }

    // ======== epilogue: logits_hp(11) + final softmax ========
    logits_rows(g_W_out_hp, bouthp, g_h_hp, HHP, g_logits_hp, rO0, rO1,
                sred, tid, lane, warp);
    GSYNC();
    if (b == 0) {
        float lv = (tid < V) ? __ldcg(g_logits_hp + tid) : 0.f;
        softmax_v(lv, out + DEPTH * V + (DEPTH - 1) * V, s_aa + V,
                  sred, sbc, tid, lane, warp);
    }
}

// ---------------- launch ----------------
extern "C" void kernel_launch(void* const* d_in, const int* in_sizes, int n_in,
                              void* d_out, int out_size) {
    const float* x_a      = (const float*)d_in[0];
    const float* x_hp     = (const float*)d_in[1];
    const float* W_ih_a   = (const float*)d_in[2];
    const float* W_hh_a   = (const float*)d_in[3];
    const float* b_ih_a   = (const float*)d_in[4];
    const float* b_hh_a   = (const float*)d_in[5];
    const float* W_out_a  = (const float*)d_in[6];
    const float* b_out_a  = (const float*)d_in[7];
    const float* W_sum    = (const float*)d_in[8];
    const float* b_sum    = (const float*)d_in[9];
    const float* W_ih_hp  = (const float*)d_in[10];
    const float* W_hh_hp  = (const float*)d_in[11];
    const float* b_ih_hp  = (const float*)d_in[12];
    const float* b_hh_hp  = (const float*)d_in[13];
    const float* W_out_hp = (const float*)d_in[14];
    const float* b_out_hp = (const float*)d_in[15];
    float* out = (float*)d_out;

    convert_kernel<<<2048, 256>>>(W_ih_a, W_hh_a, W_out_a, W_sum, W_ih_hp, W_out_hp);
    transpose_kernel<<<(HA * V / 8 + 255) / 256, 256>>>(W_out_a);
    persist_kernel<<<NB, NT>>>(x_a, x_hp, W_hh_hp, b_ih_a, b_hh_a, b_out_a, b_sum,
                               b_ih_hp, b_hh_hp, b_out_hp, out);
}